// round 6
// baseline (speedup 1.0000x reference)
#include <cuda_runtime.h>
#include <cuda_bf16.h>
#include <cstdint>

#define N_VARS_MAX    1000000
#define N_CONSTRS_MAX 500000
#define MAX_RED_BLOCKS 4096

// Zero-initialized at module load; reduce_kernel restores zeros after each use,
// so every kernel_launch call sees ax == 0 (graph-replay safe, deterministic).
__device__ float g_ax[N_CONSTRS_MAX];
__device__ float g_partials[MAX_RED_BLOCKS];   // overwritten every call before read

// ---------------------------------------------------------------------------
// Kernel 1: fused sigmoid + scatter.
//   ax[cidx] += coeff * sigmoid(pred[vidx])
// 4 nnz per thread, plain loads, exact grid (best measured config).
// Structural floor: ~1 L1tex wavefront per gather lane + per RED lane.
// ---------------------------------------------------------------------------
__device__ __forceinline__ void red_add_f32(float* addr, float val)
{
    asm volatile("red.global.add.f32 [%0], %1;" :: "l"(addr), "f"(val) : "memory");
}

__device__ __forceinline__ float sigmoidf_fast(float x)
{
    return 1.0f / (1.0f + __expf(-x));
}

__global__ void scatter_kernel(const float* __restrict__ pred,
                               const int*   __restrict__ constr_idx,
                               const int*   __restrict__ var_idx,
                               const float* __restrict__ coeff,
                               int nnz)
{
    int nvec = nnz >> 2;
    int i = blockIdx.x * blockDim.x + threadIdx.x;
    if (i < nvec) {
        int4   ci = reinterpret_cast<const int4*>(constr_idx)[i];
        int4   vi = reinterpret_cast<const int4*>(var_idx)[i];
        float4 co = reinterpret_cast<const float4*>(coeff)[i];

        // 4 independent gathers first (MLP=4)
        float x0 = __ldg(&pred[vi.x]);
        float x1 = __ldg(&pred[vi.y]);
        float x2 = __ldg(&pred[vi.z]);
        float x3 = __ldg(&pred[vi.w]);

        red_add_f32(&g_ax[ci.x], co.x * sigmoidf_fast(x0));
        red_add_f32(&g_ax[ci.y], co.y * sigmoidf_fast(x1));
        red_add_f32(&g_ax[ci.z], co.z * sigmoidf_fast(x2));
        red_add_f32(&g_ax[ci.w], co.w * sigmoidf_fast(x3));
    }
    // tail (nnz % 4)
    if (i == 0) {
        for (int j = nvec << 2; j < nnz; j++)
            red_add_f32(&g_ax[constr_idx[j]],
                        coeff[j] * sigmoidf_fast(__ldg(&pred[var_idx[j]])));
    }
}

// ---------------------------------------------------------------------------
// Kernel 2: violations + block reduce -> plain STG of per-block partial.
// No atomics, no fences, no tickets. Restores ax := 0 for the next call.
// ---------------------------------------------------------------------------
__global__ void reduce_kernel(const float* __restrict__ rhs,
                              const int*   __restrict__ sense,
                              int n_constrs)
{
    float local = 0.0f;
    int nc4 = n_constrs >> 2;
    int i = blockIdx.x * blockDim.x + threadIdx.x;

    if (i < nc4) {
        float4 ax = reinterpret_cast<const float4*>(g_ax)[i];
        float4 r  = reinterpret_cast<const float4*>(rhs)[i];
        int4   s  = reinterpret_cast<const int4*>(sense)[i];

        float d0 = ax.x - r.x, d1 = ax.y - r.y, d2 = ax.z - r.z, d3 = ax.w - r.w;
        float v0 = (s.x == 1) ? fmaxf(d0, 0.f) : (s.x == 2) ? fmaxf(-d0, 0.f) : (s.x == 3) ? fabsf(d0) : 0.f;
        float v1 = (s.y == 1) ? fmaxf(d1, 0.f) : (s.y == 2) ? fmaxf(-d1, 0.f) : (s.y == 3) ? fabsf(d1) : 0.f;
        float v2 = (s.z == 1) ? fmaxf(d2, 0.f) : (s.z == 2) ? fmaxf(-d2, 0.f) : (s.z == 3) ? fabsf(d2) : 0.f;
        float v3 = (s.w == 1) ? fmaxf(d3, 0.f) : (s.w == 2) ? fmaxf(-d3, 0.f) : (s.w == 3) ? fabsf(d3) : 0.f;
        local = (v0 + v1) + (v2 + v3);

        // restore the zero invariant for the next call
        reinterpret_cast<float4*>(g_ax)[i] = make_float4(0.f, 0.f, 0.f, 0.f);
    }
    // scalar tail (n_constrs % 4), also restores zeros
    if (blockIdx.x == 0 && threadIdx.x == 0) {
        for (int j = nc4 << 2; j < n_constrs; j++) {
            float d = g_ax[j] - rhs[j];
            g_ax[j] = 0.0f;
            int s = sense[j];
            local += (s == 1) ? fmaxf(d, 0.f) : (s == 2) ? fmaxf(-d, 0.f) : (s == 3) ? fabsf(d) : 0.f;
        }
    }

    // warp reduce
    #pragma unroll
    for (int off = 16; off > 0; off >>= 1)
        local += __shfl_xor_sync(0xFFFFFFFFu, local, off);

    __shared__ float warp_sums[32];
    int lane = threadIdx.x & 31;
    int wid  = threadIdx.x >> 5;
    if (lane == 0) warp_sums[wid] = local;
    __syncthreads();
    int nwarps = blockDim.x >> 5;

    if (wid == 0) {
        float b = (lane < nwarps) ? warp_sums[lane] : 0.0f;
        #pragma unroll
        for (int off = 16; off > 0; off >>= 1)
            b += __shfl_xor_sync(0xFFFFFFFFu, b, off);
        if (lane == 0)
            g_partials[blockIdx.x] = b;   // plain store, spread addresses
    }
}

// ---------------------------------------------------------------------------
// Kernel 3: finalize — sum partials in double, write mean.
// ---------------------------------------------------------------------------
__global__ void finalize_kernel(float* __restrict__ out, int n_partials, int n_constrs)
{
    double local = 0.0;
    for (int i = threadIdx.x; i < n_partials; i += blockDim.x)
        local += (double)g_partials[i];

    // warp reduce (double)
    #pragma unroll
    for (int off = 16; off > 0; off >>= 1)
        local += __shfl_xor_sync(0xFFFFFFFFu, local, off);

    __shared__ double warp_sums[32];
    int lane = threadIdx.x & 31;
    int wid  = threadIdx.x >> 5;
    if (lane == 0) warp_sums[wid] = local;
    __syncthreads();
    int nwarps = blockDim.x >> 5;
    if (wid == 0) {
        double b = (lane < nwarps) ? warp_sums[lane] : 0.0;
        #pragma unroll
        for (int off = 16; off > 0; off >>= 1)
            b += __shfl_xor_sync(0xFFFFFFFFu, b, off);
        if (lane == 0)
            out[0] = (float)(b / (double)n_constrs);
    }
}

// ---------------------------------------------------------------------------
// Launch: three kernels (scatter, reduce, finalize).
// ---------------------------------------------------------------------------
extern "C" void kernel_launch(void* const* d_in, const int* in_sizes, int n_in,
                              void* d_out, int out_size)
{
    const float* pred       = (const float*)d_in[0];
    const int*   constr_idx = (const int*)  d_in[1];
    const int*   var_idx    = (const int*)  d_in[2];
    const float* coeff      = (const float*)d_in[3];
    const float* rhs        = (const float*)d_in[4];
    const int*   sense      = (const int*)  d_in[5];

    int nnz       = in_sizes[1];
    int n_constrs = in_sizes[4];

    // 1) fused sigmoid + scatter — 4 nnz per thread, exact grid
    {
        int threads = 256;
        int nvec    = nnz >> 2;
        int blocks  = (nvec + threads - 1) / threads;
        if (blocks < 1) blocks = 1;
        scatter_kernel<<<blocks, threads>>>(pred, constr_idx, var_idx, coeff, nnz);
    }

    // 2) reduce — one float4 per thread, plain-STG partials
    int red_blocks;
    {
        int threads = 256;
        int work    = n_constrs >> 2;
        red_blocks  = (work + threads - 1) / threads;
        if (red_blocks < 1) red_blocks = 1;
        if (red_blocks > MAX_RED_BLOCKS) red_blocks = MAX_RED_BLOCKS; // safety (not hit at these sizes)
        reduce_kernel<<<red_blocks, threads>>>(rhs, sense, n_constrs);
    }

    // 3) finalize — single block
    finalize_kernel<<<1, 512>>>((float*)d_out, red_blocks, n_constrs);
}

// round 7
// speedup vs baseline: 1.0183x; 1.0183x over previous
#include <cuda_runtime.h>
#include <cuda_bf16.h>
#include <cstdint>

#define N_VARS_MAX    1000000
#define N_CONSTRS_MAX 500000

// Zero-initialized at module load; reduce_kernel restores zeros after each use,
// so every kernel_launch call sees ax == 0 (graph-replay safe, deterministic).
__device__ float        g_ax[N_CONSTRS_MAX];
__device__ double       g_sum;          // reset by last reduce block each call
__device__ unsigned int g_done;         // wraps back to 0 via atomicInc

// ---------------------------------------------------------------------------
// Kernel 1: fused sigmoid + scatter.
//   ax[cidx] += coeff * sigmoid(pred[vidx])
// 4 nnz per thread, plain loads, exact grid, 512-thread blocks.
// L2-slot-bound (ncu: L2=91%): ~1 gather sector + 1 atomic op per nnz is the
// structural floor; nothing here is removable without adding L2 traffic.
// ---------------------------------------------------------------------------
__device__ __forceinline__ void red_add_f32(float* addr, float val)
{
    asm volatile("red.global.add.f32 [%0], %1;" :: "l"(addr), "f"(val) : "memory");
}

__device__ __forceinline__ float sigmoidf_fast(float x)
{
    return 1.0f / (1.0f + __expf(-x));
}

__global__ __launch_bounds__(512) void scatter_kernel(
    const float* __restrict__ pred,
    const int*   __restrict__ constr_idx,
    const int*   __restrict__ var_idx,
    const float* __restrict__ coeff,
    int nnz)
{
    int nvec = nnz >> 2;
    int i = blockIdx.x * blockDim.x + threadIdx.x;
    if (i < nvec) {
        int4   ci = reinterpret_cast<const int4*>(constr_idx)[i];
        int4   vi = reinterpret_cast<const int4*>(var_idx)[i];
        float4 co = reinterpret_cast<const float4*>(coeff)[i];

        // 4 independent gathers first (MLP=4)
        float x0 = __ldg(&pred[vi.x]);
        float x1 = __ldg(&pred[vi.y]);
        float x2 = __ldg(&pred[vi.z]);
        float x3 = __ldg(&pred[vi.w]);

        red_add_f32(&g_ax[ci.x], co.x * sigmoidf_fast(x0));
        red_add_f32(&g_ax[ci.y], co.y * sigmoidf_fast(x1));
        red_add_f32(&g_ax[ci.z], co.z * sigmoidf_fast(x2));
        red_add_f32(&g_ax[ci.w], co.w * sigmoidf_fast(x3));
    }
    // tail (nnz % 4) — empty at these sizes, kept for generality
    if (i == 0) {
        for (int j = nvec << 2; j < nnz; j++)
            red_add_f32(&g_ax[constr_idx[j]],
                        coeff[j] * sigmoidf_fast(__ldg(&pred[var_idx[j]])));
    }
}

// ---------------------------------------------------------------------------
// Kernel 2: violations + reduce + finalize + RESTORE (ax := 0, g_sum := 0).
// R5's fused ticket epilogue (measured best). One float4 per thread.
// ---------------------------------------------------------------------------
__global__ void reduce_kernel(const float* __restrict__ rhs,
                              const int*   __restrict__ sense,
                              int n_constrs,
                              float* __restrict__ out,
                              int n_blocks)
{
    float local = 0.0f;
    int nc4 = n_constrs >> 2;
    int i = blockIdx.x * blockDim.x + threadIdx.x;

    if (i < nc4) {
        float4 ax = reinterpret_cast<const float4*>(g_ax)[i];
        float4 r  = reinterpret_cast<const float4*>(rhs)[i];
        int4   s  = reinterpret_cast<const int4*>(sense)[i];

        float d0 = ax.x - r.x, d1 = ax.y - r.y, d2 = ax.z - r.z, d3 = ax.w - r.w;
        float v0 = (s.x == 1) ? fmaxf(d0, 0.f) : (s.x == 2) ? fmaxf(-d0, 0.f) : (s.x == 3) ? fabsf(d0) : 0.f;
        float v1 = (s.y == 1) ? fmaxf(d1, 0.f) : (s.y == 2) ? fmaxf(-d1, 0.f) : (s.y == 3) ? fabsf(d1) : 0.f;
        float v2 = (s.z == 1) ? fmaxf(d2, 0.f) : (s.z == 2) ? fmaxf(-d2, 0.f) : (s.z == 3) ? fabsf(d2) : 0.f;
        float v3 = (s.w == 1) ? fmaxf(d3, 0.f) : (s.w == 2) ? fmaxf(-d3, 0.f) : (s.w == 3) ? fabsf(d3) : 0.f;
        local = (v0 + v1) + (v2 + v3);

        // restore the zero invariant for the next call
        reinterpret_cast<float4*>(g_ax)[i] = make_float4(0.f, 0.f, 0.f, 0.f);
    }
    // scalar tail (n_constrs % 4), also restores zeros
    if (blockIdx.x == 0 && threadIdx.x == 0) {
        for (int j = nc4 << 2; j < n_constrs; j++) {
            float d = g_ax[j] - rhs[j];
            g_ax[j] = 0.0f;
            int s = sense[j];
            local += (s == 1) ? fmaxf(d, 0.f) : (s == 2) ? fmaxf(-d, 0.f) : (s == 3) ? fabsf(d) : 0.f;
        }
    }

    // warp reduce
    #pragma unroll
    for (int off = 16; off > 0; off >>= 1)
        local += __shfl_xor_sync(0xFFFFFFFFu, local, off);

    __shared__ float warp_sums[32];
    int lane = threadIdx.x & 31;
    int wid  = threadIdx.x >> 5;
    if (lane == 0) warp_sums[wid] = local;
    __syncthreads();
    int nwarps = blockDim.x >> 5;

    __shared__ bool is_last;
    if (wid == 0) {
        float b = (lane < nwarps) ? warp_sums[lane] : 0.0f;
        #pragma unroll
        for (int off = 16; off > 0; off >>= 1)
            b += __shfl_xor_sync(0xFFFFFFFFu, b, off);
        if (lane == 0) {
            atomicAdd(&g_sum, (double)b);
            __threadfence();
            // wraps to 0 after the last block -> g_done invariant restored
            unsigned int ticket = atomicInc(&g_done, (unsigned int)(n_blocks - 1));
            is_last = (ticket == (unsigned int)(n_blocks - 1));
        }
    }
    __syncthreads();
    if (is_last && threadIdx.x == 0) {
        out[0] = (float)(g_sum / (double)n_constrs);
        g_sum = 0.0;   // restore for next call
    }
}

// ---------------------------------------------------------------------------
// Launch: two kernels.
// ---------------------------------------------------------------------------
extern "C" void kernel_launch(void* const* d_in, const int* in_sizes, int n_in,
                              void* d_out, int out_size)
{
    const float* pred       = (const float*)d_in[0];
    const int*   constr_idx = (const int*)  d_in[1];
    const int*   var_idx    = (const int*)  d_in[2];
    const float* coeff      = (const float*)d_in[3];
    const float* rhs        = (const float*)d_in[4];
    const int*   sense      = (const int*)  d_in[5];

    int nnz       = in_sizes[1];
    int n_constrs = in_sizes[4];

    // 1) fused sigmoid + scatter — 4 nnz per thread, 512-thread blocks
    {
        int threads = 512;
        int nvec    = nnz >> 2;
        int blocks  = (nvec + threads - 1) / threads;
        if (blocks < 1) blocks = 1;
        scatter_kernel<<<blocks, threads>>>(pred, constr_idx, var_idx, coeff, nnz);
    }

    // 2) reduce + finalize + state restore — one float4 per thread
    {
        int threads = 256;
        int work    = n_constrs >> 2;
        int blocks  = (work + threads - 1) / threads;
        if (blocks < 1) blocks = 1;
        reduce_kernel<<<blocks, threads>>>(rhs, sense, n_constrs, (float*)d_out, blocks);
    }
}

// round 8
// speedup vs baseline: 1.0362x; 1.0176x over previous
#include <cuda_runtime.h>
#include <cuda_bf16.h>
#include <cstdint>

#define N_VARS_MAX    1000000
#define N_CONSTRS_MAX 500000

// Zero-initialized at module load; reduce_kernel restores zeros after each use,
// so every kernel_launch call sees ax == 0 (graph-replay safe, deterministic).
__device__ float        g_ax[N_CONSTRS_MAX];
__device__ double       g_sum;          // reset by last reduce block each call
__device__ unsigned int g_done;         // wraps back to 0 via atomicInc

// ---------------------------------------------------------------------------
// Kernel 1: fused sigmoid + scatter.
//   ax[cidx] += coeff * sigmoid(pred[vidx])
// 4 nnz per thread, plain loads, exact grid, 256-thread blocks.
// __launch_bounds__(256, 8): cap regs at 32 so 64 warps/SM fit -> more
// outstanding L2 requests (scatter is L2-slot-bound at 91% LTS util).
// ---------------------------------------------------------------------------
__device__ __forceinline__ void red_add_f32(float* addr, float val)
{
    asm volatile("red.global.add.f32 [%0], %1;" :: "l"(addr), "f"(val) : "memory");
}

__device__ __forceinline__ float sigmoidf_fast(float x)
{
    return 1.0f / (1.0f + __expf(-x));
}

__global__ __launch_bounds__(256, 8) void scatter_kernel(
    const float* __restrict__ pred,
    const int*   __restrict__ constr_idx,
    const int*   __restrict__ var_idx,
    const float* __restrict__ coeff,
    int nnz)
{
    int nvec = nnz >> 2;
    int i = blockIdx.x * blockDim.x + threadIdx.x;
    if (i < nvec) {
        int4   ci = reinterpret_cast<const int4*>(constr_idx)[i];
        int4   vi = reinterpret_cast<const int4*>(var_idx)[i];
        float4 co = reinterpret_cast<const float4*>(coeff)[i];

        // 4 independent gathers first (MLP=4)
        float x0 = __ldg(&pred[vi.x]);
        float x1 = __ldg(&pred[vi.y]);
        float x2 = __ldg(&pred[vi.z]);
        float x3 = __ldg(&pred[vi.w]);

        red_add_f32(&g_ax[ci.x], co.x * sigmoidf_fast(x0));
        red_add_f32(&g_ax[ci.y], co.y * sigmoidf_fast(x1));
        red_add_f32(&g_ax[ci.z], co.z * sigmoidf_fast(x2));
        red_add_f32(&g_ax[ci.w], co.w * sigmoidf_fast(x3));
    }
    // tail (nnz % 4) — empty at these sizes, kept for generality
    if (i == 0) {
        for (int j = nvec << 2; j < nnz; j++)
            red_add_f32(&g_ax[constr_idx[j]],
                        coeff[j] * sigmoidf_fast(__ldg(&pred[var_idx[j]])));
    }
}

// ---------------------------------------------------------------------------
// Kernel 2: violations + reduce + finalize + RESTORE (ax := 0, g_sum := 0).
// 512-thread blocks -> 245 blocks: halves the serialized ticket chain.
// One float4 per thread, no grid-stride loop.
// ---------------------------------------------------------------------------
__global__ __launch_bounds__(512) void reduce_kernel(
    const float* __restrict__ rhs,
    const int*   __restrict__ sense,
    int n_constrs,
    float* __restrict__ out,
    int n_blocks)
{
    float local = 0.0f;
    int nc4 = n_constrs >> 2;
    int i = blockIdx.x * blockDim.x + threadIdx.x;

    if (i < nc4) {
        float4 ax = reinterpret_cast<const float4*>(g_ax)[i];
        float4 r  = reinterpret_cast<const float4*>(rhs)[i];
        int4   s  = reinterpret_cast<const int4*>(sense)[i];

        float d0 = ax.x - r.x, d1 = ax.y - r.y, d2 = ax.z - r.z, d3 = ax.w - r.w;
        float v0 = (s.x == 1) ? fmaxf(d0, 0.f) : (s.x == 2) ? fmaxf(-d0, 0.f) : (s.x == 3) ? fabsf(d0) : 0.f;
        float v1 = (s.y == 1) ? fmaxf(d1, 0.f) : (s.y == 2) ? fmaxf(-d1, 0.f) : (s.y == 3) ? fabsf(d1) : 0.f;
        float v2 = (s.z == 1) ? fmaxf(d2, 0.f) : (s.z == 2) ? fmaxf(-d2, 0.f) : (s.z == 3) ? fabsf(d2) : 0.f;
        float v3 = (s.w == 1) ? fmaxf(d3, 0.f) : (s.w == 2) ? fmaxf(-d3, 0.f) : (s.w == 3) ? fabsf(d3) : 0.f;
        local = (v0 + v1) + (v2 + v3);

        // restore the zero invariant for the next call
        reinterpret_cast<float4*>(g_ax)[i] = make_float4(0.f, 0.f, 0.f, 0.f);
    }
    // scalar tail (n_constrs % 4), also restores zeros
    if (blockIdx.x == 0 && threadIdx.x == 0) {
        for (int j = nc4 << 2; j < n_constrs; j++) {
            float d = g_ax[j] - rhs[j];
            g_ax[j] = 0.0f;
            int s = sense[j];
            local += (s == 1) ? fmaxf(d, 0.f) : (s == 2) ? fmaxf(-d, 0.f) : (s == 3) ? fabsf(d) : 0.f;
        }
    }

    // warp reduce
    #pragma unroll
    for (int off = 16; off > 0; off >>= 1)
        local += __shfl_xor_sync(0xFFFFFFFFu, local, off);

    __shared__ float warp_sums[32];
    int lane = threadIdx.x & 31;
    int wid  = threadIdx.x >> 5;
    if (lane == 0) warp_sums[wid] = local;
    __syncthreads();
    int nwarps = blockDim.x >> 5;

    __shared__ bool is_last;
    if (wid == 0) {
        float b = (lane < nwarps) ? warp_sums[lane] : 0.0f;
        #pragma unroll
        for (int off = 16; off > 0; off >>= 1)
            b += __shfl_xor_sync(0xFFFFFFFFu, b, off);
        if (lane == 0) {
            atomicAdd(&g_sum, (double)b);
            __threadfence();
            // wraps to 0 after the last block -> g_done invariant restored
            unsigned int ticket = atomicInc(&g_done, (unsigned int)(n_blocks - 1));
            is_last = (ticket == (unsigned int)(n_blocks - 1));
        }
    }
    __syncthreads();
    if (is_last && threadIdx.x == 0) {
        out[0] = (float)(g_sum / (double)n_constrs);
        g_sum = 0.0;   // restore for next call
    }
}

// ---------------------------------------------------------------------------
// Launch: two kernels.
// ---------------------------------------------------------------------------
extern "C" void kernel_launch(void* const* d_in, const int* in_sizes, int n_in,
                              void* d_out, int out_size)
{
    const float* pred       = (const float*)d_in[0];
    const int*   constr_idx = (const int*)  d_in[1];
    const int*   var_idx    = (const int*)  d_in[2];
    const float* coeff      = (const float*)d_in[3];
    const float* rhs        = (const float*)d_in[4];
    const int*   sense      = (const int*)  d_in[5];

    int nnz       = in_sizes[1];
    int n_constrs = in_sizes[4];

    // 1) fused sigmoid + scatter — 4 nnz per thread, 256-thread blocks, occ-8
    {
        int threads = 256;
        int nvec    = nnz >> 2;
        int blocks  = (nvec + threads - 1) / threads;
        if (blocks < 1) blocks = 1;
        scatter_kernel<<<blocks, threads>>>(pred, constr_idx, var_idx, coeff, nnz);
    }

    // 2) reduce + finalize + state restore — one float4 per thread, 512-thr blocks
    {
        int threads = 512;
        int work    = n_constrs >> 2;
        int blocks  = (work + threads - 1) / threads;
        if (blocks < 1) blocks = 1;
        reduce_kernel<<<blocks, threads>>>(rhs, sense, n_constrs, (float*)d_out, blocks);
    }
}